// round 9
// baseline (speedup 1.0000x reference)
#include <cuda_runtime.h>
#include <cstdint>

// ============================================================================
// EdgeClassifier: out = relu([emb[h], emb[t]] @ W1^T + b1) @ W2^T + b2
// E=500000, D=128, HIDDEN=256, NUM_CLASSES=32, fp32 in/out.
// R8: persistent CTAs; next-tile A gathered via raw cp.async overlapped with
// current tile's GEMM2/reduce tail; A tf32 conversion folded into GEMM1
// fragment loads; reduce scratch moved to W1 buf (2 passes).
// ============================================================================

#define TILE_M 128
#define DIMD   128
#define HID    256
#define NCLS   32
#define KC     32
#define NCHUNK (HID / KC)              // 8

#define SAW 260                        // A row stride (words), %32==4 conflict-free
#define SBW 36                         // W1 chunk row stride,  %32==4 conflict-free
#define SW2 268                        // W2 row stride,        %32==12 conflict-free

#define W1CH_WORDS (256 * SBW)         // 9216 words / chunk
#define W2_WORDS   (NCLS * SW2)        // 8576 words

// SMEM byte offsets
#define SM_B1    0
#define SM_B2    1024
#define SM_A     2048                              // 128 x 260 x 4 = 133120
#define SM_BUF0  (SM_A + TILE_M * SAW * 4)         // 135168
#define SM_BUF1  (SM_BUF0 + W1CH_WORDS * 4)        // 172032
#define SM_TOTAL (SM_BUF1 + W1CH_WORDS * 4)        // 208896

__device__ __align__(16) uint32_t g_w1t[NCHUNK * W1CH_WORDS];
__device__ __align__(16) uint32_t g_w2t[W2_WORDS];
__device__ int g_is64;

__device__ __forceinline__ uint32_t f2tf32(float f) {
    uint32_t r;
    asm("cvt.rna.tf32.f32 %0, %1;" : "=r"(r) : "f"(f));
    return r;
}
__device__ __forceinline__ uint32_t smem_u32(const void* p) {
    uint32_t a;
    asm("{ .reg .u64 t; cvta.to.shared.u64 t, %1; cvt.u32.u64 %0, t; }"
        : "=r"(a) : "l"(p));
    return a;
}
__device__ __forceinline__ void cp16(uint32_t dst, const void* src) {
    asm volatile("cp.async.cg.shared.global [%0], [%1], 16;"
                 :: "r"(dst), "l"(src) : "memory");
}
__device__ __forceinline__ void cp_commit() {
    asm volatile("cp.async.commit_group;" ::: "memory");
}
template <int N>
__device__ __forceinline__ void cp_wait() {
    asm volatile("cp.async.wait_group %0;" :: "n"(N) : "memory");
}
__device__ __forceinline__ void mma8(float* c, const uint32_t* a,
                                     uint32_t b0, uint32_t b1) {
    asm volatile(
        "mma.sync.aligned.m16n8k8.row.col.f32.tf32.tf32.f32 "
        "{%0,%1,%2,%3}, {%4,%5,%6,%7}, {%8,%9}, {%0,%1,%2,%3};"
        : "+f"(c[0]), "+f"(c[1]), "+f"(c[2]), "+f"(c[3])
        : "r"(a[0]), "r"(a[1]), "r"(a[2]), "r"(a[3]), "r"(b0), "r"(b1));
}

// ---- pre-kernel: idx-width detect + weight tf32 pre-convert ----------------
__global__ void prep_kernel(const float* __restrict__ W1,
                            const float* __restrict__ W2,
                            const unsigned int* __restrict__ p) {
    if (blockIdx.x == 0) {
        unsigned v = (threadIdx.x < 128) ? p[2 * threadIdx.x + 1] : 0u;
        int anynz = __syncthreads_or(v != 0u);
        if (threadIdx.x == 0) g_is64 = anynz ? 0 : 1;
    }
    const int i = blockIdx.x * 256 + threadIdx.x;
    if (i < NCHUNK * W1CH_WORDS) {
        const int kc = i / W1CH_WORDS, rem = i % W1CH_WORDS;
        const int row = rem / SBW, col = rem % SBW;
        g_w1t[i] = (col < KC) ? f2tf32(W1[row * HID + kc * KC + col]) : 0u;
    }
    if (i < W2_WORDS) {
        const int row = i / SW2, col = i % SW2;
        g_w2t[i] = (col < HID) ? f2tf32(W2[row * HID + col]) : 0u;
    }
}

// ============================================================================
__global__ __launch_bounds__(256, 1)
void edge_mlp_kernel(const float* __restrict__ emb,
                     const void*  __restrict__ eidx,
                     const float* __restrict__ b1,
                     const float* __restrict__ b2,
                     float* __restrict__ out,
                     int E, int tiles) {
    extern __shared__ char smem[];
    float*    sb1 = (float*)(smem + SM_B1);
    float*    sb2 = (float*)(smem + SM_B2);
    uint32_t* Asm = (uint32_t*)(smem + SM_A);
    const uint32_t sb  = smem_u32(smem);
    const uint32_t sbA = sb + SM_A;

    const int tid  = threadIdx.x;
    const int wid  = tid >> 5;
    const int lane = tid & 31;
    const int g    = lane >> 2;
    const int t    = lane & 3;
    const int is64 = g_is64;

    sb1[tid] = b1[tid];
    if (tid < NCLS) sb2[tid] = b2[tid];

    const int half  = wid & 1;      // gather: head/tail half
    const int rbase = wid >> 1;     // gather: row offset 0..3

    // Issue raw-fp32 gather of tile tl's A via cp.async (one group).
    auto gather_issue = [&](int tl) {
        long long node_l = -1;
        const int r0 = rbase + 4 * lane;
        const int e0 = tl * TILE_M + r0;
        if (tl < tiles && e0 < E) {
            const long long ofs = half ? (long long)E + e0 : (long long)e0;
            node_l = is64 ? ((const long long*)eidx)[ofs]
                          : (long long)((const int*)eidx)[ofs];
        }
        #pragma unroll 8
        for (int j = 0; j < 32; j++) {
            const long long node = __shfl_sync(0xffffffffu, node_l, j);
            if (node >= 0) {
                const int r = rbase + 4 * j;
                cp16(sbA + (r * SAW + half * 128 + lane * 4) * 4,
                     emb + node * DIMD + lane * 4);
            }
        }
        cp_commit();
    };
    auto w1_issue = [&](int kc, uint32_t dst) {
        const uint32_t* src = g_w1t + kc * W1CH_WORDS;
        #pragma unroll
        for (int s = 0; s < W1CH_WORDS / 4; s += 256)
            cp16(dst + (s + tid) * 16, src + (s + tid) * 4);
        cp_commit();
    };
    auto w2_issue = [&]() {
        const uint32_t d = sb + SM_BUF0;
        for (int s = tid; s < W2_WORDS / 4; s += 256)
            cp16(d + s * 16, g_w2t + s * 4);
        cp_commit();
    };

    // Prologue: gather(tile0) + W1 chunks 0,1.
    gather_issue(blockIdx.x);
    w1_issue(0, sb + SM_BUF0);
    w1_issue(1, sb + SM_BUF1);

    const int mwb = (wid & 1) * 64;
    const int nwb = (wid >> 1) * 64;

    for (int tile = blockIdx.x; tile < tiles; tile += gridDim.x) {
        cp_wait<0>();
        __syncthreads();                 // A + chunks 0,1 resident & visible

        float acc[4][8][4];
        #pragma unroll
        for (int mt = 0; mt < 4; mt++)
            #pragma unroll
            for (int nt = 0; nt < 8; nt++)
                #pragma unroll
                for (int j = 0; j < 4; j++) acc[mt][nt][j] = 0.f;

        // ---- GEMM1: warp tile 64x64, cvt.rna on A-frag loads --------------
        #pragma unroll 1
        for (int kc = 0; kc < NCHUNK; kc++) {
            if (kc >= 2) { cp_wait<1>(); __syncthreads(); }

            const uint32_t* Bsm =
                (const uint32_t*)(smem + ((kc & 1) ? SM_BUF1 : SM_BUF0));

            #pragma unroll
            for (int s = 0; s < KC / 8; s++) {
                const int k0 = s * 8;
                const int ka = kc * KC + k0;
                uint32_t af[4][4];
                #pragma unroll
                for (int mt = 0; mt < 4; mt++) {
                    const int r = mwb + mt * 16;
                    af[mt][0] = f2tf32(__uint_as_float(Asm[(r + g)     * SAW + ka + t]));
                    af[mt][1] = f2tf32(__uint_as_float(Asm[(r + g + 8) * SAW + ka + t]));
                    af[mt][2] = f2tf32(__uint_as_float(Asm[(r + g)     * SAW + ka + t + 4]));
                    af[mt][3] = f2tf32(__uint_as_float(Asm[(r + g + 8) * SAW + ka + t + 4]));
                }
                #pragma unroll
                for (int nt = 0; nt < 8; nt++) {
                    const int n = nwb + nt * 8 + g;
                    const uint32_t b0  = Bsm[n * SBW + k0 + t];
                    const uint32_t b1r = Bsm[n * SBW + k0 + t + 4];
                    #pragma unroll
                    for (int mt = 0; mt < 4; mt++)
                        mma8(acc[mt][nt], af[mt], b0, b1r);
                }
            }
            __syncthreads();             // all reads of buf[kc&1] done

            if (kc < NCHUNK - 2)
                w1_issue(kc + 2, sb + ((kc & 1) ? SM_BUF1 : SM_BUF0));
            else if (kc == NCHUNK - 2)
                w2_issue();              // into BUF0 (freed by kc==6)
        }

        // A region now dead: prefetch next tile's A under the GEMM2 tail.
        gather_issue(tile + gridDim.x);
        cp_wait<1>();                    // W2 resident (gather outstanding)
        __syncthreads();

        // ---- GEMM2 from registers: per-warp K=64 partials -----------------
        const uint32_t* Wsm = (const uint32_t*)(smem + SM_BUF0);
        float acc2p[4][4][4];
        #pragma unroll
        for (int mt = 0; mt < 4; mt++)
            #pragma unroll
            for (int n2b = 0; n2b < 4; n2b++)
                #pragma unroll
                for (int j = 0; j < 4; j++) acc2p[mt][n2b][j] = 0.f;

        const int srcA = (lane & ~3) | (t >> 1);
        const int srcB = srcA + 2;
        const bool odd = (t & 1) != 0;

        #pragma unroll
        for (int nt = 0; nt < 8; nt++) {
            const int colb = nwb + nt * 8;
            const float bi0 = sb1[colb + 2 * t];
            const float bi1 = sb1[colb + 2 * t + 1];
            uint32_t bf[4][2];
            #pragma unroll
            for (int n2b = 0; n2b < 4; n2b++) {
                bf[n2b][0] = Wsm[(n2b * 8 + g) * SW2 + colb + t];
                bf[n2b][1] = Wsm[(n2b * 8 + g) * SW2 + colb + t + 4];
            }
            #pragma unroll
            for (int mt = 0; mt < 4; mt++) {
                const float* c = acc[mt][nt];
                const uint32_t h0 = f2tf32(fmaxf(c[0] + bi0, 0.f));
                const uint32_t h1 = f2tf32(fmaxf(c[1] + bi1, 0.f));
                const uint32_t h2 = f2tf32(fmaxf(c[2] + bi0, 0.f));
                const uint32_t h3 = f2tf32(fmaxf(c[3] + bi1, 0.f));
                const uint32_t x0 = __shfl_sync(0xffffffffu, h0, srcA);
                const uint32_t x1 = __shfl_sync(0xffffffffu, h1, srcA);
                const uint32_t x2 = __shfl_sync(0xffffffffu, h2, srcA);
                const uint32_t x3 = __shfl_sync(0xffffffffu, h3, srcA);
                const uint32_t y0 = __shfl_sync(0xffffffffu, h0, srcB);
                const uint32_t y1 = __shfl_sync(0xffffffffu, h1, srcB);
                const uint32_t y2 = __shfl_sync(0xffffffffu, h2, srcB);
                const uint32_t y3 = __shfl_sync(0xffffffffu, h3, srcB);
                uint32_t a[4];
                a[0] = odd ? x1 : x0;
                a[1] = odd ? x3 : x2;
                a[2] = odd ? y1 : y0;
                a[3] = odd ? y3 : y2;
                #pragma unroll
                for (int n2b = 0; n2b < 4; n2b++)
                    mma8(acc2p[mt][n2b], a, bf[n2b][0], bf[n2b][1]);
            }
        }

        // ---- Cross-warp K-reduce via BUF1 scratch, 2 passes (mt pairs) ----
        float* scr = (float*)(smem + SM_BUF1);
        const int rmgrp = wid & 1;
        const int rmth  = (wid >> 1) & 1;
        const int rq    = wid >> 2;

        #pragma unroll
        for (int p = 0; p < 2; p++) {
            #pragma unroll
            for (int mth = 0; mth < 2; mth++)
                #pragma unroll
                for (int n2b = 0; n2b < 4; n2b++)
                    #pragma unroll
                    for (int ci = 0; ci < 4; ci++)
                        scr[wid * 1024 + (mth * 16 + n2b * 4 + ci) * 32 + lane] =
                            acc2p[2 * p + mth][n2b][ci];
            __syncthreads();

            if (p == 0) w1_issue(0, sb + SM_BUF0);   // next tile's chunk 0

            #pragma unroll
            for (int nn = 0; nn < 2; nn++) {
                const int n2b = rq * 2 + nn;
                float s[4];
                #pragma unroll
                for (int ci = 0; ci < 4; ci++) {
                    const int reg = rmth * 16 + n2b * 4 + ci;
                    float v = scr[(0 * 2 + rmgrp) * 1024 + reg * 32 + lane];
                    v += scr[(1 * 2 + rmgrp) * 1024 + reg * 32 + lane];
                    v += scr[(2 * 2 + rmgrp) * 1024 + reg * 32 + lane];
                    v += scr[(3 * 2 + rmgrp) * 1024 + reg * 32 + lane];
                    s[ci] = v;
                }
                const int cc = n2b * 8 + 2 * t;
                const float bz0 = sb2[cc], bz1 = sb2[cc + 1];
                const int r0 = tile * TILE_M + rmgrp * 64 + (2 * p + rmth) * 16 + g;
                if (r0 < E)
                    *(float2*)(out + (size_t)r0 * NCLS + cc) =
                        make_float2(s[0] + bz0, s[1] + bz1);
                if (r0 + 8 < E)
                    *(float2*)(out + (size_t)(r0 + 8) * NCLS + cc) =
                        make_float2(s[2] + bz0, s[3] + bz1);
            }
            __syncthreads();             // scratch reads done before reuse
        }

        w1_issue(1, sb + SM_BUF1);       // next tile's chunk 1 (scratch freed)
    }

    cp_wait<0>();                        // drain outstanding async copies
    __syncthreads();
}

// ============================================================================
extern "C" void kernel_launch(void* const* d_in, const int* in_sizes, int n_in,
                              void* d_out, int out_size) {
    const float* emb  = (const float*)d_in[0];
    const void*  eidx = d_in[1];
    const float* W1   = (const float*)d_in[2];
    const float* b1   = (const float*)d_in[3];
    const float* W2   = (const float*)d_in[4];
    const float* b2   = (const float*)d_in[5];
    float* out = (float*)d_out;

    const int E = in_sizes[1] / 2;
    const int tiles = (E + TILE_M - 1) / TILE_M;

    int dev = 0, nsm = 148;
    cudaGetDevice(&dev);
    cudaDeviceGetAttribute(&nsm, cudaDevAttrMultiProcessorCount, dev);
    const int grid = tiles < nsm ? tiles : nsm;

    cudaFuncSetAttribute(edge_mlp_kernel,
                         cudaFuncAttributeMaxDynamicSharedMemorySize, SM_TOTAL);

    prep_kernel<<<(NCHUNK * W1CH_WORDS + 255) / 256, 256>>>(
        W1, W2, (const unsigned int*)eidx);
    edge_mlp_kernel<<<grid, 256, SM_TOTAL>>>(emb, eidx, b1, b2, out, E, tiles);
}

// round 10
// speedup vs baseline: 1.2021x; 1.2021x over previous
#include <cuda_runtime.h>
#include <cstdint>

// ============================================================================
// EdgeClassifier: out = relu([emb[h], emb[t]] @ W1^T + b1) @ W2^T + b2
// E=500000, D=128, HIDDEN=256, NUM_CLASSES=32, fp32 in/out.
// R9 = R7 skeleton + k-interleaved operand layouts so every MMA fragment
// load is a single LDS.64 (pairs (k+t, k+t+4) stored adjacent). Strides
// chosen for conflict-free LDS.64 half-warp phases (stride % 32 == 8).
// ============================================================================

#define TILE_M 128
#define DIMD   128
#define HID    256
#define NCLS   32
#define KC     32
#define NCHUNK (HID / KC)              // 8

#define SAW 264                        // A row stride (words), %32==8
#define SBW 40                         // W1 chunk row stride,  %32==8
#define SW2 264                        // W2 row stride,        %32==8

#define W1CH_WORDS (256 * SBW)         // 10240 words / chunk
#define W2_WORDS   (NCLS * SW2)        // 8448 words

// SMEM byte offsets
#define SM_B1    0
#define SM_B2    1024
#define SM_A     2048                              // 128 x 264 x 4 = 135168
#define SM_BUF0  (SM_A + TILE_M * SAW * 4)         // 137216
#define SM_BUF1  (SM_BUF0 + W1CH_WORDS * 4)        // 178176
#define SM_TOTAL (SM_BUF1 + W1CH_WORDS * 4)        // 219136

__device__ __align__(16) uint32_t g_w1t[NCHUNK * W1CH_WORDS];
__device__ __align__(16) uint32_t g_w2t[W2_WORDS];
__device__ int g_is64;

__device__ __forceinline__ uint32_t f2tf32(float f) {
    uint32_t r;
    asm("cvt.rna.tf32.f32 %0, %1;" : "=r"(r) : "f"(f));
    return r;
}
__device__ __forceinline__ uint32_t smem_u32(const void* p) {
    uint32_t a;
    asm("{ .reg .u64 t; cvta.to.shared.u64 t, %1; cvt.u32.u64 %0, t; }"
        : "=r"(a) : "l"(p));
    return a;
}
__device__ __forceinline__ void cp16(uint32_t dst, const void* src) {
    asm volatile("cp.async.cg.shared.global [%0], [%1], 16;"
                 :: "r"(dst), "l"(src) : "memory");
}
__device__ __forceinline__ void cp_commit() {
    asm volatile("cp.async.commit_group;" ::: "memory");
}
template <int N>
__device__ __forceinline__ void cp_wait() {
    asm volatile("cp.async.wait_group %0;" :: "n"(N) : "memory");
}
__device__ __forceinline__ void mma8(float* c, const uint32_t* a,
                                     uint32_t b0, uint32_t b1) {
    asm volatile(
        "mma.sync.aligned.m16n8k8.row.col.f32.tf32.tf32.f32 "
        "{%0,%1,%2,%3}, {%4,%5,%6,%7}, {%8,%9}, {%0,%1,%2,%3};"
        : "+f"(c[0]), "+f"(c[1]), "+f"(c[2]), "+f"(c[3])
        : "r"(a[0]), "r"(a[1]), "r"(a[2]), "r"(a[3]), "r"(b0), "r"(b1));
}

// k-interleave within each 8-col group: word q in group holds
// col = 8G + (q>>1) + 4*(q&1), i.e. layout [c, c+4, c+1, c+5, c+2, c+6, ...]
// so the pair (k+t, k+4+t) a fragment needs sits at words (2t, 2t+1).

// ---- pre-kernel: idx-width detect + weight tf32 pre-convert (permuted) -----
__global__ void prep_kernel(const float* __restrict__ W1,
                            const float* __restrict__ W2,
                            const unsigned int* __restrict__ p) {
    if (blockIdx.x == 0) {
        unsigned v = (threadIdx.x < 128) ? p[2 * threadIdx.x + 1] : 0u;
        int anynz = __syncthreads_or(v != 0u);
        if (threadIdx.x == 0) g_is64 = anynz ? 0 : 1;
    }
    const int i = blockIdx.x * 256 + threadIdx.x;
    if (i < NCHUNK * W1CH_WORDS) {
        const int kc = i / W1CH_WORDS, rem = i % W1CH_WORDS;
        const int row = rem / SBW, w = rem % SBW;
        uint32_t v = 0u;
        if (w < KC) {
            const int G = w >> 3, q = w & 7;
            const int col = kc * KC + G * 8 + (q >> 1) + 4 * (q & 1);
            v = f2tf32(W1[row * HID + col]);
        }
        g_w1t[i] = v;
    }
    if (i < W2_WORDS) {
        const int row = i / SW2, w = i % SW2;
        uint32_t v = 0u;
        if (w < HID) {
            const int G = w >> 3, q = w & 7;
            const int col = G * 8 + (q >> 1) + 4 * (q & 1);
            v = f2tf32(W2[row * HID + col]);
        }
        g_w2t[i] = v;
    }
}

// ============================================================================
__global__ __launch_bounds__(256, 1)
void edge_mlp_kernel(const float* __restrict__ emb,
                     const void*  __restrict__ eidx,
                     const float* __restrict__ b1,
                     const float* __restrict__ b2,
                     float* __restrict__ out,
                     int E) {
    extern __shared__ char smem[];
    float*    sb1 = (float*)(smem + SM_B1);
    float*    sb2 = (float*)(smem + SM_B2);
    uint32_t* Asm = (uint32_t*)(smem + SM_A);
    const uint32_t sb = smem_u32(smem);

    const int tid  = threadIdx.x;
    const int wid  = tid >> 5;
    const int lane = tid & 31;
    const int g    = lane >> 2;
    const int t    = lane & 3;
    const int tile = blockIdx.x;
    const int is64 = g_is64;

    sb1[tid] = b1[tid];
    if (tid < NCLS) sb2[tid] = b2[tid];

    // Prologue: async-stage W1 chunks 0,1 (overlaps the gather LDGs below).
    {
        const uint32_t d0 = sb + SM_BUF0, d1 = sb + SM_BUF1;
        #pragma unroll
        for (int s = 0; s < W1CH_WORDS / 4; s += 256)
            cp16(d0 + (s + tid) * 16, g_w1t + (s + tid) * 4);
        cp_commit();
        #pragma unroll
        for (int s = 0; s < W1CH_WORDS / 4; s += 256)
            cp16(d1 + (s + tid) * 16, g_w1t + W1CH_WORDS + (s + tid) * 4);
        cp_commit();
    }

    // ---- Gather A[128][256], tf32 + k-interleave via lane-pair bfly -------
    // Lane l holds cols 4l..4l+3. After exchanging with partner (l^1),
    // even lane stores [my.x, pr.x, my.y, pr.y], odd [pr.z, my.z, pr.w, my.w]
    // at word lane*4 — exactly the interleaved layout, contiguous STS.128.
    {
        const int half  = wid & 1;
        const int rbase = wid >> 1;
        long long node_l = -1;
        {
            const int r = rbase + 4 * lane;
            const int e = tile * TILE_M + r;
            if (e < E) {
                const long long ofs = half ? (long long)E + e : (long long)e;
                node_l = is64 ? ((const long long*)eidx)[ofs]
                              : (long long)((const int*)eidx)[ofs];
            }
        }
        const bool oddl = (lane & 1) != 0;
        #pragma unroll 4
        for (int j = 0; j < 32; j++) {
            const int r = rbase + 4 * j;
            const long long node = __shfl_sync(0xffffffffu, node_l, j);
            float4 v = make_float4(0.f, 0.f, 0.f, 0.f);
            if (node >= 0) v = ((const float4*)(emb + node * DIMD))[lane];
            const uint32_t u0 = f2tf32(v.x), u1 = f2tf32(v.y);
            const uint32_t u2 = f2tf32(v.z), u3 = f2tf32(v.w);
            const uint32_t s0 = __shfl_xor_sync(0xffffffffu, u0, 1);
            const uint32_t s1 = __shfl_xor_sync(0xffffffffu, u1, 1);
            const uint32_t s2 = __shfl_xor_sync(0xffffffffu, u2, 1);
            const uint32_t s3 = __shfl_xor_sync(0xffffffffu, u3, 1);
            uint4 wv;
            if (oddl) wv = make_uint4(s2, u2, s3, u3);
            else      wv = make_uint4(u0, s0, u1, s1);
            *(uint4*)(Asm + r * SAW + half * 128 + lane * 4) = wv;
        }
    }

    // ---- GEMM1: D1[128,256] = A @ W1^T; warp tile 64x64 (2m x 4n warps) ----
    const int mwb = (wid & 1) * 64;
    const int nwb = (wid >> 1) * 64;

    float acc[4][8][4];
    #pragma unroll
    for (int mt = 0; mt < 4; mt++)
        #pragma unroll
        for (int nt = 0; nt < 8; nt++)
            #pragma unroll
            for (int j = 0; j < 4; j++) acc[mt][nt][j] = 0.f;

    #pragma unroll 1
    for (int kc = 0; kc < NCHUNK; kc++) {
        cp_wait<1>();
        __syncthreads();

        const uint32_t* Bsm =
            (const uint32_t*)(smem + ((kc & 1) ? SM_BUF1 : SM_BUF0));

        #pragma unroll
        for (int s = 0; s < KC / 8; s++) {
            const int k0 = s * 8;
            const int ka = kc * KC + k0;
            uint2 pa[4], pb[4];
            #pragma unroll
            for (int mt = 0; mt < 4; mt++) {
                const int r = mwb + mt * 16;
                pa[mt] = *(const uint2*)(Asm + (r + g)     * SAW + ka + 2 * t);
                pb[mt] = *(const uint2*)(Asm + (r + g + 8) * SAW + ka + 2 * t);
            }
            #pragma unroll
            for (int nt = 0; nt < 8; nt++) {
                const int n = nwb + nt * 8 + g;
                const uint2 bb = *(const uint2*)(Bsm + n * SBW + k0 + 2 * t);
                #pragma unroll
                for (int mt = 0; mt < 4; mt++) {
                    uint32_t a4[4] = {pa[mt].x, pb[mt].x, pa[mt].y, pb[mt].y};
                    mma8(acc[mt][nt], a4, bb.x, bb.y);
                }
            }
        }
        __syncthreads();

        if (kc < NCHUNK - 2) {
            const uint32_t d = sb + ((kc & 1) ? SM_BUF1 : SM_BUF0);
            const uint32_t* src = g_w1t + (kc + 2) * W1CH_WORDS;
            #pragma unroll
            for (int s = 0; s < W1CH_WORDS / 4; s += 256)
                cp16(d + (s + tid) * 16, src + (s + tid) * 4);
            cp_commit();
        } else if (kc == NCHUNK - 2) {
            const uint32_t d = sb + SM_BUF0;     // buf0 free: prefetch W2
            for (int s = tid; s < W2_WORDS / 4; s += 256)
                cp16(d + s * 16, g_w2t + s * 4);
            cp_commit();
        }
    }

    // ---- GEMM2 from registers: per-warp K=64 partials ----------------------
    cp_wait<0>();                        // W2 resident in BUF0
    const uint32_t* Wsm = (const uint32_t*)(smem + SM_BUF0);

    float acc2p[4][4][4];
    #pragma unroll
    for (int mt = 0; mt < 4; mt++)
        #pragma unroll
        for (int n2b = 0; n2b < 4; n2b++)
            #pragma unroll
            for (int j = 0; j < 4; j++) acc2p[mt][n2b][j] = 0.f;

    const int srcA = (lane & ~3) | (t >> 1);
    const int srcB = srcA + 2;
    const bool odd = (t & 1) != 0;

    #pragma unroll
    for (int nt = 0; nt < 8; nt++) {
        const int colb = nwb + nt * 8;
        const float bi0 = sb1[colb + 2 * t];
        const float bi1 = sb1[colb + 2 * t + 1];
        uint2 bf[4];
        #pragma unroll
        for (int n2b = 0; n2b < 4; n2b++)
            bf[n2b] = *(const uint2*)(Wsm + (n2b * 8 + g) * SW2 + colb + 2 * t);
        #pragma unroll
        for (int mt = 0; mt < 4; mt++) {
            const float* c = acc[mt][nt];
            const uint32_t h0 = f2tf32(fmaxf(c[0] + bi0, 0.f));
            const uint32_t h1 = f2tf32(fmaxf(c[1] + bi1, 0.f));
            const uint32_t h2 = f2tf32(fmaxf(c[2] + bi0, 0.f));
            const uint32_t h3 = f2tf32(fmaxf(c[3] + bi1, 0.f));
            const uint32_t x0 = __shfl_sync(0xffffffffu, h0, srcA);
            const uint32_t x1 = __shfl_sync(0xffffffffu, h1, srcA);
            const uint32_t x2 = __shfl_sync(0xffffffffu, h2, srcA);
            const uint32_t x3 = __shfl_sync(0xffffffffu, h3, srcA);
            const uint32_t y0 = __shfl_sync(0xffffffffu, h0, srcB);
            const uint32_t y1 = __shfl_sync(0xffffffffu, h1, srcB);
            const uint32_t y2 = __shfl_sync(0xffffffffu, h2, srcB);
            const uint32_t y3 = __shfl_sync(0xffffffffu, h3, srcB);
            uint32_t a[4];
            a[0] = odd ? x1 : x0;
            a[1] = odd ? x3 : x2;
            a[2] = odd ? y1 : y0;
            a[3] = odd ? y3 : y2;
            #pragma unroll
            for (int n2b = 0; n2b < 4; n2b++)
                mma8(acc2p[mt][n2b], a, bf[n2b].x, bf[n2b].y);
        }
    }

    // ---- Cross-warp K-reduce via scratch over dead A region ---------------
    {
        float* scr = (float*)(smem + SM_A);
        #pragma unroll
        for (int mt = 0; mt < 4; mt++)
            #pragma unroll
            for (int n2b = 0; n2b < 4; n2b++)
                #pragma unroll
                for (int ci = 0; ci < 4; ci++)
                    scr[wid * 2048 + (mt * 16 + n2b * 4 + ci) * 32 + lane] =
                        acc2p[mt][n2b][ci];
        __syncthreads();

        const int mgrp = wid & 1;
        const int wq   = wid >> 1;
        #pragma unroll
        for (int n2b = 0; n2b < 4; n2b++) {
            float s[4];
            #pragma unroll
            for (int ci = 0; ci < 4; ci++) {
                const int reg = wq * 16 + n2b * 4 + ci;
                float v = scr[(0 * 2 + mgrp) * 2048 + reg * 32 + lane];
                v += scr[(1 * 2 + mgrp) * 2048 + reg * 32 + lane];
                v += scr[(2 * 2 + mgrp) * 2048 + reg * 32 + lane];
                v += scr[(3 * 2 + mgrp) * 2048 + reg * 32 + lane];
                s[ci] = v;
            }
            const int cc = n2b * 8 + 2 * t;
            const float bz0 = sb2[cc], bz1 = sb2[cc + 1];
            const int r0 = tile * TILE_M + mgrp * 64 + wq * 16 + g;
            if (r0 < E)
                *(float2*)(out + (size_t)r0 * NCLS + cc) =
                    make_float2(s[0] + bz0, s[1] + bz1);
            if (r0 + 8 < E)
                *(float2*)(out + (size_t)(r0 + 8) * NCLS + cc) =
                    make_float2(s[2] + bz0, s[3] + bz1);
        }
    }
}

// ============================================================================
extern "C" void kernel_launch(void* const* d_in, const int* in_sizes, int n_in,
                              void* d_out, int out_size) {
    const float* emb  = (const float*)d_in[0];
    const void*  eidx = d_in[1];
    const float* W1   = (const float*)d_in[2];
    const float* b1   = (const float*)d_in[3];
    const float* W2   = (const float*)d_in[4];
    const float* b2   = (const float*)d_in[5];
    float* out = (float*)d_out;

    const int E = in_sizes[1] / 2;
    const int tiles = (E + TILE_M - 1) / TILE_M;

    cudaFuncSetAttribute(edge_mlp_kernel,
                         cudaFuncAttributeMaxDynamicSharedMemorySize, SM_TOTAL);

    prep_kernel<<<(NCHUNK * W1CH_WORDS + 255) / 256, 256>>>(
        W1, W2, (const unsigned int*)eidx);
    edge_mlp_kernel<<<tiles, 256, SM_TOTAL>>>(emb, eidx, b1, b2, out, E);
}

// round 11
// speedup vs baseline: 1.4344x; 1.1932x over previous
#include <cuda_runtime.h>
#include <cstdint>

// ============================================================================
// EdgeClassifier: out = relu([emb[h], emb[t]] @ W1^T + b1) @ W2^T + b2
// E=500000, D=128, HIDDEN=256, NUM_CLASSES=32, fp32 in/out.
// R10 = R7 (best: 487us) + shuffle-free GEMM2 fragment conversion via
// k-relabeling: thread t carries k=(2t,2t+1) in both A and B fragments of
// the second GEMM (mma.sync sums all 8 k-slots regardless of labeling), so
// the C->A conversion is a pure register reordering and W2 fragment loads
// become adjacent-pair LDS.64 from the natural layout.
// ============================================================================

#define TILE_M 128
#define DIMD   128
#define HID    256
#define NCLS   32
#define KC     32
#define NCHUNK (HID / KC)              // 8

#define SAW 260                        // A row stride (words), %32==4 conflict-free
#define SBW 36                         // W1 chunk row stride,  %32==4 conflict-free
#define SW2 264                        // W2 row stride, %32==8: uint2 frag loads
                                       // hit banks {8g+2t, +1} all-distinct/phase

#define W1CH_WORDS (256 * SBW)         // 9216 words / chunk
#define W2_WORDS   (NCLS * SW2)        // 8448 words

// SMEM byte offsets
#define SM_B1    0
#define SM_B2    1024
#define SM_A     2048                              // 128 x 260 x 4 = 133120
#define SM_BUF0  (SM_A + TILE_M * SAW * 4)         // 135168
#define SM_BUF1  (SM_BUF0 + W1CH_WORDS * 4)        // 172032
#define SM_TOTAL (SM_BUF1 + W1CH_WORDS * 4)        // 208896

__device__ __align__(16) uint32_t g_w1t[NCHUNK * W1CH_WORDS];
__device__ __align__(16) uint32_t g_w2t[W2_WORDS];
__device__ int g_is64;

__device__ __forceinline__ uint32_t f2tf32(float f) {
    uint32_t r;
    asm("cvt.rna.tf32.f32 %0, %1;" : "=r"(r) : "f"(f));
    return r;
}
__device__ __forceinline__ uint32_t smem_u32(const void* p) {
    uint32_t a;
    asm("{ .reg .u64 t; cvta.to.shared.u64 t, %1; cvt.u32.u64 %0, t; }"
        : "=r"(a) : "l"(p));
    return a;
}
__device__ __forceinline__ void cp16(uint32_t dst, const void* src) {
    asm volatile("cp.async.cg.shared.global [%0], [%1], 16;"
                 :: "r"(dst), "l"(src) : "memory");
}
__device__ __forceinline__ void cp_commit() {
    asm volatile("cp.async.commit_group;" ::: "memory");
}
template <int N>
__device__ __forceinline__ void cp_wait() {
    asm volatile("cp.async.wait_group %0;" :: "n"(N) : "memory");
}
__device__ __forceinline__ void mma8(float* c, const uint32_t* a,
                                     uint32_t b0, uint32_t b1) {
    asm volatile(
        "mma.sync.aligned.m16n8k8.row.col.f32.tf32.tf32.f32 "
        "{%0,%1,%2,%3}, {%4,%5,%6,%7}, {%8,%9}, {%0,%1,%2,%3};"
        : "+f"(c[0]), "+f"(c[1]), "+f"(c[2]), "+f"(c[3])
        : "r"(a[0]), "r"(a[1]), "r"(a[2]), "r"(a[3]), "r"(b0), "r"(b1));
}
__device__ __forceinline__ void mma8s(float* c, uint32_t a0, uint32_t a1,
                                      uint32_t a2, uint32_t a3,
                                      uint32_t b0, uint32_t b1) {
    asm volatile(
        "mma.sync.aligned.m16n8k8.row.col.f32.tf32.tf32.f32 "
        "{%0,%1,%2,%3}, {%4,%5,%6,%7}, {%8,%9}, {%0,%1,%2,%3};"
        : "+f"(c[0]), "+f"(c[1]), "+f"(c[2]), "+f"(c[3])
        : "r"(a0), "r"(a1), "r"(a2), "r"(a3), "r"(b0), "r"(b1));
}

// ---- pre-kernel: idx-width detect + weight tf32 pre-convert ----------------
__global__ void prep_kernel(const float* __restrict__ W1,
                            const float* __restrict__ W2,
                            const unsigned int* __restrict__ p) {
    if (blockIdx.x == 0) {
        unsigned v = (threadIdx.x < 128) ? p[2 * threadIdx.x + 1] : 0u;
        int anynz = __syncthreads_or(v != 0u);
        if (threadIdx.x == 0) g_is64 = anynz ? 0 : 1;
    }
    const int i = blockIdx.x * 256 + threadIdx.x;
    if (i < NCHUNK * W1CH_WORDS) {
        const int kc = i / W1CH_WORDS, rem = i % W1CH_WORDS;
        const int row = rem / SBW, col = rem % SBW;
        g_w1t[i] = (col < KC) ? f2tf32(W1[row * HID + kc * KC + col]) : 0u;
    }
    if (i < W2_WORDS) {
        const int row = i / SW2, col = i % SW2;
        g_w2t[i] = (col < HID) ? f2tf32(W2[row * HID + col]) : 0u;
    }
}

// ============================================================================
__global__ __launch_bounds__(256, 1)
void edge_mlp_kernel(const float* __restrict__ emb,
                     const void*  __restrict__ eidx,
                     const float* __restrict__ b1,
                     const float* __restrict__ b2,
                     float* __restrict__ out,
                     int E) {
    extern __shared__ char smem[];
    float*    sb1 = (float*)(smem + SM_B1);
    float*    sb2 = (float*)(smem + SM_B2);
    uint32_t* Asm = (uint32_t*)(smem + SM_A);
    const uint32_t sb = smem_u32(smem);

    const int tid  = threadIdx.x;
    const int wid  = tid >> 5;
    const int lane = tid & 31;
    const int g    = lane >> 2;
    const int t    = lane & 3;
    const int tile = blockIdx.x;
    const int is64 = g_is64;

    sb1[tid] = b1[tid];
    if (tid < NCLS) sb2[tid] = b2[tid];

    // Prologue: async-stage W1 chunks 0,1.
    {
        const uint32_t d0 = sb + SM_BUF0, d1 = sb + SM_BUF1;
        #pragma unroll
        for (int s = 0; s < W1CH_WORDS / 4; s += 256)
            cp16(d0 + (s + tid) * 16, g_w1t + (s + tid) * 4);
        cp_commit();
        #pragma unroll
        for (int s = 0; s < W1CH_WORDS / 4; s += 256)
            cp16(d1 + (s + tid) * 16, g_w1t + W1CH_WORDS + (s + tid) * 4);
        cp_commit();
    }

    // ---- Gather A[128][256]: warp handles one half (head/tail), rows
    //      r = (wid>>1) + 4j. Indices preloaded lane-parallel, shfl-broadcast.
    {
        const int half  = wid & 1;
        const int rbase = wid >> 1;
        long long node_l = -1;
        {
            const int r = rbase + 4 * lane;
            const int e = tile * TILE_M + r;
            if (e < E) {
                const long long ofs = half ? (long long)E + e : (long long)e;
                node_l = is64 ? ((const long long*)eidx)[ofs]
                              : (long long)((const int*)eidx)[ofs];
            }
        }
        #pragma unroll 4
        for (int j = 0; j < 32; j++) {
            const int r = rbase + 4 * j;
            const long long node = __shfl_sync(0xffffffffu, node_l, j);
            float4 v = make_float4(0.f, 0.f, 0.f, 0.f);
            if (node >= 0) v = ((const float4*)(emb + node * DIMD))[lane];
            *(uint4*)(Asm + r * SAW + half * 128 + lane * 4) =
                make_uint4(f2tf32(v.x), f2tf32(v.y), f2tf32(v.z), f2tf32(v.w));
        }
    }

    // ---- GEMM1: D1[128,256] = A @ W1^T; warp tile 64x64 (2m x 4n warps) ----
    const int mwb = (wid & 1) * 64;
    const int nwb = (wid >> 1) * 64;

    float acc[4][8][4];
    #pragma unroll
    for (int mt = 0; mt < 4; mt++)
        #pragma unroll
        for (int nt = 0; nt < 8; nt++)
            #pragma unroll
            for (int j = 0; j < 4; j++) acc[mt][nt][j] = 0.f;

    #pragma unroll 1
    for (int kc = 0; kc < NCHUNK; kc++) {
        cp_wait<1>();
        __syncthreads();

        const uint32_t* Bsm =
            (const uint32_t*)(smem + ((kc & 1) ? SM_BUF1 : SM_BUF0));

        #pragma unroll
        for (int s = 0; s < KC / 8; s++) {
            const int k0 = s * 8;
            const int ka = kc * KC + k0;
            uint32_t af[4][4];
            #pragma unroll
            for (int mt = 0; mt < 4; mt++) {
                const int r = mwb + mt * 16;
                af[mt][0] = Asm[(r + g)     * SAW + ka + t];
                af[mt][1] = Asm[(r + g + 8) * SAW + ka + t];
                af[mt][2] = Asm[(r + g)     * SAW + ka + t + 4];
                af[mt][3] = Asm[(r + g + 8) * SAW + ka + t + 4];
            }
            #pragma unroll
            for (int nt = 0; nt < 8; nt++) {
                const int n = nwb + nt * 8 + g;
                const uint32_t b0  = Bsm[n * SBW + k0 + t];
                const uint32_t b1r = Bsm[n * SBW + k0 + t + 4];
                #pragma unroll
                for (int mt = 0; mt < 4; mt++) mma8(acc[mt][nt], af[mt], b0, b1r);
            }
        }
        __syncthreads();

        if (kc < NCHUNK - 2) {
            const uint32_t d = sb + ((kc & 1) ? SM_BUF1 : SM_BUF0);
            const uint32_t* src = g_w1t + (kc + 2) * W1CH_WORDS;
            #pragma unroll
            for (int s = 0; s < W1CH_WORDS / 4; s += 256)
                cp16(d + (s + tid) * 16, src + (s + tid) * 4);
            cp_commit();
        } else if (kc == NCHUNK - 2) {
            const uint32_t d = sb + SM_BUF0;     // buf0 free: prefetch W2
            for (int s = tid; s < W2_WORDS / 4; s += 256)
                cp16(d + s * 16, g_w2t + s * 4);
            cp_commit();
        }
    }

    // ---- GEMM2 from registers: per-warp K=64 partials, SHUFFLE-FREE -------
    // k-relabel: thread t carries k=(2t, 2t+1) in both operands.
    //   A-frag slots: a0=(row g,   k 2t) = h0, a1=(row g+8, k 2t) = h2,
    //                 a2=(row g,  k 2t+1)= h1, a3=(row g+8, k 2t+1)= h3
    //   B-frag: W2[n][colb+2t], W2[n][colb+2t+1] — adjacent LDS.64, natural.
    cp_wait<0>();                        // W2 resident in BUF0
    const uint32_t* Wsm = (const uint32_t*)(smem + SM_BUF0);

    float acc2p[4][4][4];
    #pragma unroll
    for (int mt = 0; mt < 4; mt++)
        #pragma unroll
        for (int n2b = 0; n2b < 4; n2b++)
            #pragma unroll
            for (int j = 0; j < 4; j++) acc2p[mt][n2b][j] = 0.f;

    #pragma unroll
    for (int nt = 0; nt < 8; nt++) {
        const int colb = nwb + nt * 8;
        const float bi0 = sb1[colb + 2 * t];
        const float bi1 = sb1[colb + 2 * t + 1];
        uint2 bf[4];
        #pragma unroll
        for (int n2b = 0; n2b < 4; n2b++)
            bf[n2b] = *(const uint2*)(Wsm + (n2b * 8 + g) * SW2 + colb + 2 * t);
        #pragma unroll
        for (int mt = 0; mt < 4; mt++) {
            const float* c = acc[mt][nt];
            const uint32_t h0 = f2tf32(fmaxf(c[0] + bi0, 0.f));
            const uint32_t h1 = f2tf32(fmaxf(c[1] + bi1, 0.f));
            const uint32_t h2 = f2tf32(fmaxf(c[2] + bi0, 0.f));
            const uint32_t h3 = f2tf32(fmaxf(c[3] + bi1, 0.f));
            #pragma unroll
            for (int n2b = 0; n2b < 4; n2b++)
                mma8s(acc2p[mt][n2b], h0, h2, h1, h3, bf[n2b].x, bf[n2b].y);
        }
    }

    // ---- Cross-warp K-reduce via scratch over dead A region ---------------
    {
        float* scr = (float*)(smem + SM_A);
        #pragma unroll
        for (int mt = 0; mt < 4; mt++)
            #pragma unroll
            for (int n2b = 0; n2b < 4; n2b++)
                #pragma unroll
                for (int ci = 0; ci < 4; ci++)
                    scr[wid * 2048 + (mt * 16 + n2b * 4 + ci) * 32 + lane] =
                        acc2p[mt][n2b][ci];
        __syncthreads();

        const int mgrp = wid & 1;
        const int wq   = wid >> 1;
        #pragma unroll
        for (int n2b = 0; n2b < 4; n2b++) {
            float s[4];
            #pragma unroll
            for (int ci = 0; ci < 4; ci++) {
                const int reg = wq * 16 + n2b * 4 + ci;
                float v = scr[(0 * 2 + mgrp) * 2048 + reg * 32 + lane];
                v += scr[(1 * 2 + mgrp) * 2048 + reg * 32 + lane];
                v += scr[(2 * 2 + mgrp) * 2048 + reg * 32 + lane];
                v += scr[(3 * 2 + mgrp) * 2048 + reg * 32 + lane];
                s[ci] = v;
            }
            const int cc = n2b * 8 + 2 * t;
            const float bz0 = sb2[cc], bz1 = sb2[cc + 1];
            const int r0 = tile * TILE_M + mgrp * 64 + wq * 16 + g;
            if (r0 < E)
                *(float2*)(out + (size_t)r0 * NCLS + cc) =
                    make_float2(s[0] + bz0, s[1] + bz1);
            if (r0 + 8 < E)
                *(float2*)(out + (size_t)(r0 + 8) * NCLS + cc) =
                    make_float2(s[2] + bz0, s[3] + bz1);
        }
    }
}

// ============================================================================
extern "C" void kernel_launch(void* const* d_in, const int* in_sizes, int n_in,
                              void* d_out, int out_size) {
    const float* emb  = (const float*)d_in[0];
    const void*  eidx = d_in[1];
    const float* W1   = (const float*)d_in[2];
    const float* b1   = (const float*)d_in[3];
    const float* W2   = (const float*)d_in[4];
    const float* b2   = (const float*)d_in[5];
    float* out = (float*)d_out;

    const int E = in_sizes[1] / 2;
    const int tiles = (E + TILE_M - 1) / TILE_M;

    cudaFuncSetAttribute(edge_mlp_kernel,
                         cudaFuncAttributeMaxDynamicSharedMemorySize, SM_TOTAL);

    prep_kernel<<<(NCHUNK * W1CH_WORDS + 255) / 256, 256>>>(
        W1, W2, (const unsigned int*)eidx);
    edge_mlp_kernel<<<tiles, 256, SM_TOTAL>>>(emb, eidx, b1, b2, out, E);
}